// round 7
// baseline (speedup 1.0000x reference)
#include <cuda_runtime.h>
#include <cuda_fp16.h>

// Problem constants (fixed shapes for this problem)
#define N_NODES 20000
#define F_IN    8
#define T_P     12
#define HID     32
#define FEAT    96      // F_IN * T_P floats per node
#define FEAT4   24      // FEAT / 4

// ---------------- device scratch (no allocations allowed) ----------------
__device__ float  g_cnt [N_NODES];               // edge in-degree (zeroed by memset)
__device__ float  g_dinv[N_NODES];               // rsqrt(cnt + 1)
__device__ float4 g_agg [N_NODES * FEAT4];       // dinv_d*x_d + sum_e dinv_s*x_s
__device__ __half g_xh  [N_NODES * FEAT];        // fp16(dinv_n * x_n)
__device__ float  g_WLz [F_IN * HID];            // Wz @ Lz_top  (8 x 32)
__device__ float  g_WLh [F_IN * HID];            // Wh @ Lh_top  (8 x 32)
__device__ float  g_blz [HID];                   // bz @ Lz_top + lz
__device__ float  g_blh [HID];                   // bh @ Lh_top + lh
__device__ float  g_probs[T_P];                  // softmax(att)

__device__ __forceinline__ float fast_tanh(float x) {
    float y;
    asm("tanh.approx.f32 %0, %1;" : "=f"(y) : "f"(x));
    return y;
}

// ---------------- kernels ----------------

// Tiny 1-block kernel: fold gate weights, biases, softmax(att).
__global__ void k_pre(const float* __restrict__ Wz, const float* __restrict__ bz,
                      const float* __restrict__ Wh, const float* __restrict__ bh,
                      const float* __restrict__ Lz, const float* __restrict__ lz,
                      const float* __restrict__ Lh, const float* __restrict__ lh,
                      const float* __restrict__ att) {
    int tid = threadIdx.x;
    if (tid < F_IN * HID) {
        int f = tid >> 5, h = tid & 31;
        float az = 0.f, ah = 0.f;
        #pragma unroll 8
        for (int k = 0; k < HID; k++) {
            az = fmaf(Wz[f * HID + k], Lz[k * HID + h], az);
            ah = fmaf(Wh[f * HID + k], Lh[k * HID + h], ah);
        }
        g_WLz[tid] = az;
        g_WLh[tid] = ah;
    }
    if (tid < HID) {
        float az = lz[tid], ah = lh[tid];
        for (int k = 0; k < HID; k++) {
            az = fmaf(bz[k], Lz[k * HID + tid], az);
            ah = fmaf(bh[k], Lh[k * HID + tid], ah);
        }
        g_blz[tid] = az;
        g_blh[tid] = ah;
    }
    if (tid == 0) {
        float m = -1e30f;
        for (int t = 0; t < T_P; t++) m = fmaxf(m, att[t]);
        float e[T_P], s = 0.f;
        for (int t = 0; t < T_P; t++) { e[t] = __expf(att[t] - m); s += e[t]; }
        float inv = 1.0f / s;
        for (int t = 0; t < T_P; t++) g_probs[t] = e[t] * inv;
    }
}

// Degree histogram (edges only; self-loop +1 folded in later). 4 edges/thread.
__global__ void k_count(const int4* __restrict__ dst4, int E4) {
    int i = blockIdx.x * blockDim.x + threadIdx.x;
    if (i < E4) {
        int4 d = __ldg(&dst4[i]);
        atomicAdd(&g_cnt[d.x], 1.0f);
        atomicAdd(&g_cnt[d.y], 1.0f);
        atomicAdd(&g_cnt[d.z], 1.0f);
        atomicAdd(&g_cnt[d.w], 1.0f);
    }
}

// Node-indexed mid pass: dinv, seed agg with self term (dinv*x, plain stores
// -> no agg memset needed), and write fp16 pre-scaled features for the scatter.
// One thread per float4 chunk (24 per node).
__global__ void k_mid(const float4* __restrict__ x4) {
    int i = blockIdx.x * blockDim.x + threadIdx.x;
    if (i >= N_NODES * FEAT4) return;
    int n = i / FEAT4;
    float dn = rsqrtf(__ldg(&g_cnt[n]) + 1.0f);
    if ((i - n * FEAT4) == 0) g_dinv[n] = dn;
    float4 v = __ldg(&x4[i]);
    v.x *= dn; v.y *= dn; v.z *= dn; v.w *= dn;
    g_agg[i] = v;                                 // self-loop seed (x dinv scale)
    __half2* xh2 = (__half2*)g_xh;
    xh2[i * 2]     = __floats2half2_rn(v.x, v.y);
    xh2[i * 2 + 1] = __floats2half2_rn(v.z, v.w);
}

// Scatter: agg[dst] += xh[src] (already dinv_s-scaled, fp16 -> f32 reds).
// 4 threads per edge, each handles 3 x 16B half-chunks (= 6 red.v4.f32).
__global__ void k_scatter(const int* __restrict__ src,
                          const int* __restrict__ dst, int E) {
    int i = blockIdx.x * blockDim.x + threadIdx.x;
    int e = i >> 2;
    if (e >= E) return;
    int sub = i & 3;
    int s = __ldg(&src[e]);
    int d = __ldg(&dst[e]);

    const uint4* xh4 = (const uint4*)g_xh + s * 12;   // 12 x 16B = 96 halves
    float4* ad = g_agg + d * FEAT4;
    #pragma unroll
    for (int k = 0; k < 3; k++) {
        int c = sub + k * 4;                      // half-chunk index 0..11
        uint4 hv = __ldg(&xh4[c]);
        float2 f0 = __half22float2(*(const __half2*)&hv.x);
        float2 f1 = __half22float2(*(const __half2*)&hv.y);
        float2 f2 = __half22float2(*(const __half2*)&hv.z);
        float2 f3 = __half22float2(*(const __half2*)&hv.w);
        asm volatile("red.global.add.v4.f32 [%0], {%1, %2, %3, %4};"
                     :: "l"(&ad[2 * c]), "f"(f0.x), "f"(f0.y), "f"(f1.x), "f"(f1.y)
                     : "memory");
        asm volatile("red.global.add.v4.f32 [%0], {%1, %2, %3, %4};"
                     :: "l"(&ad[2 * c + 1]), "f"(f2.x), "f"(f2.y), "f"(f3.x), "f"(f3.y)
                     : "memory");
    }
}

// One warp per node: full = dinv_n * agg, gates, attention, output projection.
__global__ void __launch_bounds__(256)
k_node(const float* __restrict__ Wout,
       const float* __restrict__ bout,
       float* __restrict__ out) {
    __shared__ float shT[8][FEAT];               // time-major features, per warp
    __shared__ float sWout[HID * T_P];
    __shared__ float sBout[T_P];

    const int tid  = threadIdx.x;
    const int w    = tid >> 5;
    const int lane = tid & 31;

    for (int i = tid; i < HID * T_P; i += 256) sWout[i] = Wout[i];
    if (tid < T_P) sBout[tid] = bout[tid];
    __syncthreads();

    const int node = blockIdx.x * 8 + w;
    if (node >= N_NODES) return;

    // Gate weights (lane == hidden index h).
    float wz[F_IN], wh[F_IN];
    #pragma unroll
    for (int f = 0; f < F_IN; f++) {
        wz[f] = g_WLz[f * HID + lane];
        wh[f] = g_WLh[f * HID + lane];
    }
    const float bz0 = g_blz[lane];
    const float bh0 = g_blh[lane];

    const float dn = g_dinv[node];

    // lanes 0..23 each own one float4 chunk of agg; finalize + transpose.
    if (lane < FEAT4) {
        float4 A = g_agg[node * FEAT4 + lane];
        float v[4];
        v[0] = dn * A.x; v[1] = dn * A.y; v[2] = dn * A.z; v[3] = dn * A.w;
        #pragma unroll
        for (int q = 0; q < 4; q++) {
            int idx = lane * 4 + q;              // idx = f*T_P + t
            int f = idx / T_P;
            int t = idx - f * T_P;
            shT[w][t * F_IN + f] = v[q];
        }
    }
    __syncwarp();

    float hacc = 0.f;
    #pragma unroll
    for (int t = 0; t < T_P; t++) {
        float4 xa0 = *(const float4*)&shT[w][t * F_IN];
        float4 xa1 = *(const float4*)&shT[w][t * F_IN + 4];
        float uz = bz0, uh = bh0;
        uz = fmaf(xa0.x, wz[0], uz); uh = fmaf(xa0.x, wh[0], uh);
        uz = fmaf(xa0.y, wz[1], uz); uh = fmaf(xa0.y, wh[1], uh);
        uz = fmaf(xa0.z, wz[2], uz); uh = fmaf(xa0.z, wh[2], uh);
        uz = fmaf(xa0.w, wz[3], uz); uh = fmaf(xa0.w, wh[3], uh);
        uz = fmaf(xa1.x, wz[4], uz); uh = fmaf(xa1.x, wh[4], uh);
        uz = fmaf(xa1.y, wz[5], uz); uh = fmaf(xa1.y, wh[5], uh);
        uz = fmaf(xa1.z, wz[6], uz); uh = fmaf(xa1.z, wh[6], uh);
        uz = fmaf(xa1.w, wz[7], uz); uh = fmaf(xa1.w, wh[7], uh);
        // (1 - sigmoid(uz)) = 0.5*(1 - tanh(uz/2))
        float omz = 0.5f - 0.5f * fast_tanh(0.5f * uz);
        hacc = fmaf(g_probs[t], omz * fast_tanh(uh), hacc);
    }

    __syncwarp();
    shT[w][lane] = fmaxf(hacc, 0.f);             // relu(H_accum)
    __syncwarp();

    if (lane < T_P) {
        float acc = sBout[lane];
        #pragma unroll
        for (int h = 0; h < HID; h++)
            acc = fmaf(shT[w][h], sWout[h * T_P + lane], acc);
        out[node * T_P + lane] = acc;
    }
}

// ---------------- launch ----------------
extern "C" void kernel_launch(void* const* d_in, const int* in_sizes, int n_in,
                              void* d_out, int out_size) {
    const float* x    = (const float*)d_in[0];   // (N, F_IN, T)
    const int*   ei   = (const int*)  d_in[1];   // (2, E)
    const float* Wz   = (const float*)d_in[2];
    const float* bz   = (const float*)d_in[3];
    // d_in[4], d_in[5]: Wr, br  (dead: H0 == 0)
    const float* Wh   = (const float*)d_in[6];
    const float* bh   = (const float*)d_in[7];
    const float* Lz   = (const float*)d_in[8];
    const float* lz   = (const float*)d_in[9];
    // d_in[10], d_in[11]: Lr, lr (dead)
    const float* Lh   = (const float*)d_in[12];
    const float* lh   = (const float*)d_in[13];
    const float* att  = (const float*)d_in[14];
    const float* Wout = (const float*)d_in[15];
    const float* bout = (const float*)d_in[16];
    float* out = (float*)d_out;

    int E = in_sizes[1] / 2;
    const int* src = ei;
    const int* dst = ei + E;

    // Zero only the degree histogram (agg is fully overwritten by k_mid).
    void* cptr = nullptr;
    cudaGetSymbolAddress(&cptr, g_cnt);
    cudaMemsetAsync(cptr, 0, (size_t)N_NODES * sizeof(float));

    k_pre<<<1, 256>>>(Wz, bz, Wh, bh, Lz, lz, Lh, lh, att);

    int E4 = E / 4;
    k_count<<<(E4 + 255) / 256, 256>>>((const int4*)dst, E4);

    k_mid<<<(N_NODES * FEAT4 + 255) / 256, 256>>>((const float4*)x);

    k_scatter<<<(E * 4 + 255) / 256, 256>>>(src, dst, E);

    k_node<<<(N_NODES + 7) / 8, 256>>>(Wout, bout, out);
}

// round 8
// speedup vs baseline: 1.2685x; 1.2685x over previous
#include <cuda_runtime.h>
#include <cuda_fp16.h>

// Problem constants (fixed shapes for this problem)
#define N_NODES 20000
#define F_IN    8
#define T_P     12
#define HID     32
#define FEAT    96      // F_IN * T_P floats per node
#define FEAT4   24      // FEAT / 4

// ---------------- device scratch (no allocations allowed) ----------------
__device__ float  g_cnt [N_NODES];               // edge in-degree (zeroed by memset)
__device__ float  g_dinv[N_NODES];               // rsqrt(cnt + 1)
__device__ float4 g_agg [N_NODES * FEAT4];       // dinv_d*x_d + sum_e dinv_s*x_s
__device__ __half g_xh  [N_NODES * FEAT];        // fp16(dinv_n * x_n)
__device__ float  g_WLz [F_IN * HID];            // Wz @ Lz_top  (8 x 32)
__device__ float  g_WLh [F_IN * HID];            // Wh @ Lh_top  (8 x 32)
__device__ float  g_blz [HID];                   // bz @ Lz_top + lz
__device__ float  g_blh [HID];                   // bh @ Lh_top + lh
__device__ float  g_probs[T_P];                  // softmax(att)

__device__ __forceinline__ float fast_tanh(float x) {
    float y;
    asm("tanh.approx.f32 %0, %1;" : "=f"(y) : "f"(x));
    return y;
}

// ---------------- kernels ----------------

// Degree histogram (4 edges/thread). Block 0 additionally folds the gate
// weights (WL = W @ L_top, bl = b @ L_top + l) and computes softmax(att) --
// independent of the histogram, so no ordering hazard.
__global__ void k_count_pre(const int4* __restrict__ dst4, int E4,
                            const float* __restrict__ Wz, const float* __restrict__ bz,
                            const float* __restrict__ Wh, const float* __restrict__ bh,
                            const float* __restrict__ Lz, const float* __restrict__ lz,
                            const float* __restrict__ Lh, const float* __restrict__ lh,
                            const float* __restrict__ att) {
    int i = blockIdx.x * blockDim.x + threadIdx.x;
    if (i < E4) {
        int4 d = __ldg(&dst4[i]);
        atomicAdd(&g_cnt[d.x], 1.0f);
        atomicAdd(&g_cnt[d.y], 1.0f);
        atomicAdd(&g_cnt[d.z], 1.0f);
        atomicAdd(&g_cnt[d.w], 1.0f);
    }
    if (blockIdx.x == 0) {
        int tid = threadIdx.x;
        if (tid < F_IN * HID) {
            int f = tid >> 5, h = tid & 31;
            float az = 0.f, ah = 0.f;
            #pragma unroll 8
            for (int k = 0; k < HID; k++) {
                az = fmaf(Wz[f * HID + k], Lz[k * HID + h], az);
                ah = fmaf(Wh[f * HID + k], Lh[k * HID + h], ah);
            }
            g_WLz[tid] = az;
            g_WLh[tid] = ah;
        }
        if (tid < HID) {
            float az = lz[tid], ah = lh[tid];
            for (int k = 0; k < HID; k++) {
                az = fmaf(bz[k], Lz[k * HID + tid], az);
                ah = fmaf(bh[k], Lh[k * HID + tid], ah);
            }
            g_blz[tid] = az;
            g_blh[tid] = ah;
        }
        if (tid == 0) {
            float m = -1e30f;
            for (int t = 0; t < T_P; t++) m = fmaxf(m, att[t]);
            float e[T_P], s = 0.f;
            for (int t = 0; t < T_P; t++) { e[t] = __expf(att[t] - m); s += e[t]; }
            float inv = 1.0f / s;
            for (int t = 0; t < T_P; t++) g_probs[t] = e[t] * inv;
        }
    }
}

// Node-indexed mid pass: dinv, seed agg with self term (dinv*x, plain stores
// -> no agg memset needed), and write fp16 pre-scaled features for the scatter.
// One thread per float4 chunk (24 per node).
__global__ void k_mid(const float4* __restrict__ x4) {
    int i = blockIdx.x * blockDim.x + threadIdx.x;
    if (i >= N_NODES * FEAT4) return;
    int n = i / FEAT4;
    float dn = rsqrtf(__ldg(&g_cnt[n]) + 1.0f);
    if ((i - n * FEAT4) == 0) g_dinv[n] = dn;
    float4 v = __ldg(&x4[i]);
    v.x *= dn; v.y *= dn; v.z *= dn; v.w *= dn;
    g_agg[i] = v;                                 // self-loop seed (x dinv scale)
    __half2* xh2 = (__half2*)g_xh;
    xh2[i * 2]     = __floats2half2_rn(v.x, v.y);
    xh2[i * 2 + 1] = __floats2half2_rn(v.z, v.w);
}

// Scatter: agg[dst] += xh[src] (already dinv_s-scaled, fp16 -> f32 reds).
// 8 threads per edge; lane owns chunks sub, sub+8, sub+16 so each red.v4
// wavefront (8 lanes x 16B) covers one contiguous 128B segment of agg[dst].
__global__ void k_scatter(const int* __restrict__ src,
                          const int* __restrict__ dst, int E) {
    int i = blockIdx.x * blockDim.x + threadIdx.x;
    int e = i >> 3;
    if (e >= E) return;
    int sub = i & 7;
    int s = __ldg(&src[e]);
    int d = __ldg(&dst[e]);

    const uint2* xh2 = (const uint2*)g_xh + s * FEAT4;  // 24 x 8B = 96 halves
    float4* ad = g_agg + d * FEAT4;
    #pragma unroll
    for (int k = 0; k < 3; k++) {
        int c = sub + k * 8;                      // chunk index 0..23
        uint2 hv = __ldg(&xh2[c]);
        float2 f0 = __half22float2(*(const __half2*)&hv.x);
        float2 f1 = __half22float2(*(const __half2*)&hv.y);
        asm volatile("red.global.add.v4.f32 [%0], {%1, %2, %3, %4};"
                     :: "l"(&ad[c]), "f"(f0.x), "f"(f0.y), "f"(f1.x), "f"(f1.y)
                     : "memory");
    }
}

// One warp per node: full = dinv_n * agg, gates, attention, output projection.
__global__ void __launch_bounds__(256)
k_node(const float* __restrict__ Wout,
       const float* __restrict__ bout,
       float* __restrict__ out) {
    __shared__ float shT[8][FEAT];               // time-major features, per warp
    __shared__ float sWout[HID * T_P];
    __shared__ float sBout[T_P];

    const int tid  = threadIdx.x;
    const int w    = tid >> 5;
    const int lane = tid & 31;

    for (int i = tid; i < HID * T_P; i += 256) sWout[i] = Wout[i];
    if (tid < T_P) sBout[tid] = bout[tid];
    __syncthreads();

    const int node = blockIdx.x * 8 + w;
    if (node >= N_NODES) return;

    // Gate weights (lane == hidden index h).
    float wz[F_IN], wh[F_IN];
    #pragma unroll
    for (int f = 0; f < F_IN; f++) {
        wz[f] = g_WLz[f * HID + lane];
        wh[f] = g_WLh[f * HID + lane];
    }
    const float bz0 = g_blz[lane];
    const float bh0 = g_blh[lane];

    const float dn = g_dinv[node];

    // lanes 0..23 each own one float4 chunk of agg; finalize + transpose.
    if (lane < FEAT4) {
        float4 A = g_agg[node * FEAT4 + lane];
        float v[4];
        v[0] = dn * A.x; v[1] = dn * A.y; v[2] = dn * A.z; v[3] = dn * A.w;
        #pragma unroll
        for (int q = 0; q < 4; q++) {
            int idx = lane * 4 + q;              // idx = f*T_P + t
            int f = idx / T_P;
            int t = idx - f * T_P;
            shT[w][t * F_IN + f] = v[q];
        }
    }
    __syncwarp();

    float hacc = 0.f;
    #pragma unroll
    for (int t = 0; t < T_P; t++) {
        float4 xa0 = *(const float4*)&shT[w][t * F_IN];
        float4 xa1 = *(const float4*)&shT[w][t * F_IN + 4];
        float uz = bz0, uh = bh0;
        uz = fmaf(xa0.x, wz[0], uz); uh = fmaf(xa0.x, wh[0], uh);
        uz = fmaf(xa0.y, wz[1], uz); uh = fmaf(xa0.y, wh[1], uh);
        uz = fmaf(xa0.z, wz[2], uz); uh = fmaf(xa0.z, wh[2], uh);
        uz = fmaf(xa0.w, wz[3], uz); uh = fmaf(xa0.w, wh[3], uh);
        uz = fmaf(xa1.x, wz[4], uz); uh = fmaf(xa1.x, wh[4], uh);
        uz = fmaf(xa1.y, wz[5], uz); uh = fmaf(xa1.y, wh[5], uh);
        uz = fmaf(xa1.z, wz[6], uz); uh = fmaf(xa1.z, wh[6], uh);
        uz = fmaf(xa1.w, wz[7], uz); uh = fmaf(xa1.w, wh[7], uh);
        // (1 - sigmoid(uz)) = 0.5*(1 - tanh(uz/2))
        float omz = 0.5f - 0.5f * fast_tanh(0.5f * uz);
        hacc = fmaf(g_probs[t], omz * fast_tanh(uh), hacc);
    }

    __syncwarp();
    shT[w][lane] = fmaxf(hacc, 0.f);             // relu(H_accum)
    __syncwarp();

    if (lane < T_P) {
        float acc = sBout[lane];
        #pragma unroll
        for (int h = 0; h < HID; h++)
            acc = fmaf(shT[w][h], sWout[h * T_P + lane], acc);
        out[node * T_P + lane] = acc;
    }
}

// ---------------- launch ----------------
extern "C" void kernel_launch(void* const* d_in, const int* in_sizes, int n_in,
                              void* d_out, int out_size) {
    const float* x    = (const float*)d_in[0];   // (N, F_IN, T)
    const int*   ei   = (const int*)  d_in[1];   // (2, E)
    const float* Wz   = (const float*)d_in[2];
    const float* bz   = (const float*)d_in[3];
    // d_in[4], d_in[5]: Wr, br  (dead: H0 == 0)
    const float* Wh   = (const float*)d_in[6];
    const float* bh   = (const float*)d_in[7];
    const float* Lz   = (const float*)d_in[8];
    const float* lz   = (const float*)d_in[9];
    // d_in[10], d_in[11]: Lr, lr (dead)
    const float* Lh   = (const float*)d_in[12];
    const float* lh   = (const float*)d_in[13];
    const float* att  = (const float*)d_in[14];
    const float* Wout = (const float*)d_in[15];
    const float* bout = (const float*)d_in[16];
    float* out = (float*)d_out;

    int E = in_sizes[1] / 2;
    const int* src = ei;
    const int* dst = ei + E;

    // Zero only the degree histogram (agg is fully overwritten by k_mid).
    void* cptr = nullptr;
    cudaGetSymbolAddress(&cptr, g_cnt);
    cudaMemsetAsync(cptr, 0, (size_t)N_NODES * sizeof(float));

    int E4 = E / 4;
    k_count_pre<<<(E4 + 255) / 256, 256>>>((const int4*)dst, E4,
                                           Wz, bz, Wh, bh, Lz, lz, Lh, lh, att);

    k_mid<<<(N_NODES * FEAT4 + 255) / 256, 256>>>((const float4*)x);

    k_scatter<<<(E * 8 + 255) / 256, 256>>>(src, dst, E);

    k_node<<<(N_NODES + 7) / 8, 256>>>(Wout, bout, out);
}